// round 2
// baseline (speedup 1.0000x reference)
#include <cuda_runtime.h>

#define NN   64
#define TT   128
#define NBR  16
#define NB2  32
#define NP   256
#define NS   255      // segments per branch
#define BIGF 1e30f

// Scratch (no allocations allowed in kernel_launch)
__device__ float g_proj[NN * NB2 * TT * 3];   // projected points per branch
__device__ float g_cost[NN * NB2];            // per-branch cost (BIG if no segs)

__global__ __launch_bounds__(256, 4)
void arc_branch_kernel(const float* __restrict__ traj,        // [N,T,3]
                       const float* __restrict__ road,        // [N,NBR,NP,3]
                       const unsigned char* __restrict__ maskraw /* [N,NBR,NP] bool (uint8 OR int32) */)
{
    __shared__ float rx[NP], ry[NP], rz[NP];
    __shared__ unsigned char rm[NP];
    __shared__ float sl[NP];          // seg length (0 if invalid); sl[255]=0
    __shared__ float cum[NP];         // inclusive scan of sl; cum_s(i) = i? cum[i-1] : 0
    __shared__ float px[TT], py[TT], pz[TT];
    __shared__ float tc[NP];          // traj arclength scan buffer
    __shared__ float rd[256];
    __shared__ int   ri[256];
    __shared__ float sh_entry, sh_total;
    __shared__ int   sh_mvj, sh_has;

    const int tid = threadIdx.x;
    const int b2  = blockIdx.x;       // 0..31 : [0,16) fwd, [16,32) bwd
    const int n   = blockIdx.y;
    const bool bw = (b2 >= NBR);
    const int b   = bw ? (b2 - NBR) : b2;
    const int src = bw ? (NP - 1 - tid) : tid;

    const float* rp = road + (size_t)((n * NBR + b) * NP) * 3;
    rx[tid] = rp[src * 3 + 0];
    ry[tid] = rp[src * 3 + 1];
    rz[tid] = rp[src * 3 + 2];

    // ---- mask dtype disambiguation (deterministic, data-derived):
    // lengths >= 2  =>  mask element (0,0,1) is always true.
    // uint8 storage:  byte[1] == 1.   int32 LE storage: byte[1] == 0.
    {
        const bool m32 = (maskraw[1] == 0);
        const size_t e = (size_t)(n * NBR + b) * NP + src;
        rm[tid] = m32 ? (unsigned char)(((const int*)maskraw)[e] != 0)
                      : (unsigned char)(maskraw[e] != 0);
    }
    if (tid < TT) {
        const float* pt = traj + (size_t)(n * TT + tid) * 3;
        px[tid] = pt[0]; py[tid] = pt[1]; pz[tid] = pt[2];
    }
    __syncthreads();

    // Segment lengths (masked) and trajectory segment lengths
    float slv = 0.0f;
    bool  smv = false;
    if (tid < NS) {
        smv = (rm[tid] != 0) && (rm[tid + 1] != 0);
        float dx = rx[tid + 1] - rx[tid];
        float dy = ry[tid + 1] - ry[tid];
        float dz = rz[tid + 1] - rz[tid];
        slv = smv ? sqrtf(dx * dx + dy * dy + dz * dz) : 0.0f;
    }
    sl[tid]  = slv;
    cum[tid] = slv;

    float tlv = 0.0f;
    if (tid < TT - 1) {
        float dx = px[tid + 1] - px[tid];
        float dy = py[tid + 1] - py[tid];
        float dz = pz[tid + 1] - pz[tid];
        tlv = sqrtf(dx * dx + dy * dy + dz * dz);
    }
    tc[tid] = tlv;
    __syncthreads();

    // In-place Hillis-Steele inclusive scans (road cum_s and traj cum_s together)
    #pragma unroll
    for (int off = 1; off < NP; off <<= 1) {
        float a1 = (tid >= off) ? cum[tid - off] : 0.0f;
        float a2 = (tid >= off) ? tc[tid - off]  : 0.0f;
        __syncthreads();
        cum[tid] += a1;
        tc[tid]  += a2;
        __syncthreads();
    }
    // cum_s(i) = (i==0) ? 0 : cum[i-1]; total_s = cum[NP-1] (sl[255]==0)
    // traj_cum(t) = (t==0) ? 0 : tc[t-1]

    // ---- Project p0 onto every valid segment; argmin d2 (first-index tie-break)
    const float p0x = px[0], p0y = py[0], p0z = pz[0];
    float d2 = BIGF;
    if (tid < NS) {
        float ax = rx[tid], ay = ry[tid], az = rz[tid];
        float svx = rx[tid + 1] - ax, svy = ry[tid + 1] - ay, svz = rz[tid + 1] - az;
        float svdot = fmaxf(svx * svx + svy * svy + svz * svz, 1e-12f);
        float t0 = ((p0x - ax) * svx + (p0y - ay) * svy + (p0z - az) * svz) / svdot;
        t0 = fminf(fmaxf(t0, 0.0f), 1.0f);
        float qx = ax + t0 * svx, qy = ay + t0 * svy, qz = az + t0 * svz;
        float ex = p0x - qx, ey = p0y - qy, ez = p0z - qz;
        float dd = ex * ex + ey * ey + ez * ez;
        d2 = smv ? dd : BIGF;
    }
    rd[tid] = d2;
    ri[tid] = tid;
    __syncthreads();
    #pragma unroll
    for (int s = 128; s > 0; s >>= 1) {
        if (tid < s) {
            float o = rd[tid + s]; int oi = ri[tid + s];
            if (o < rd[tid] || (o == rd[tid] && oi < ri[tid])) { rd[tid] = o; ri[tid] = oi; }
        }
        __syncthreads();
    }
    const int seg0 = ri[0];   // <= 254 thanks to tie-break (tid=255 entry is BIG,idx=255)
    __syncthreads();

    // ---- max valid segment index & has-any-segment (reduce max of (sm ? k+1 : 0))
    ri[tid] = (tid < NS && smv) ? (tid + 1) : 0;
    __syncthreads();
    #pragma unroll
    for (int s = 128; s > 0; s >>= 1) {
        if (tid < s) { int o = ri[tid + s]; if (o > ri[tid]) ri[tid] = o; }
        __syncthreads();
    }
    if (tid == 0) {
        int m   = ri[0];
        sh_mvj  = (m > 0) ? (m - 1) : 0;
        sh_has  = (m > 0);
        // entry arclength at seg0
        int k = seg0;
        float ax = rx[k], ay = ry[k], az = rz[k];
        float svx = rx[k + 1] - ax, svy = ry[k + 1] - ay, svz = rz[k + 1] - az;
        float svdot = fmaxf(svx * svx + svy * svy + svz * svz, 1e-12f);
        float t0 = ((p0x - ax) * svx + (p0y - ay) * svy + (p0z - az) * svz) / svdot;
        t0 = fminf(fmaxf(t0, 0.0f), 1.0f);
        float c0 = (k == 0) ? 0.0f : cum[k - 1];
        sh_entry = c0 + t0 * sl[k];
        sh_total = cum[NP - 1];
    }
    __syncthreads();

    const float entry = sh_entry;
    const float total = sh_total;
    const int   mvj   = sh_mvj;

    // ---- Walk trajectory along arc; project; accumulate distance
    float dist = 0.0f;
    if (tid < TT) {
        float tcs = (tid == 0) ? 0.0f : tc[tid - 1];
        float tgt = entry + tcs;
        tgt = fmaxf(fminf(tgt, total), 0.0f);
        // largest j in [0,255] with cum_s(j) <= tgt  (cum_s(0)=0 <= tgt always)
        int lo = 0, hi = NP - 1;
        #pragma unroll
        for (int it = 0; it < 8; ++it) {
            if (lo < hi) {
                int mid = (lo + hi + 1) >> 1;
                float c = cum[mid - 1];
                if (c <= tgt) lo = mid; else hi = mid - 1;
            }
        }
        int j = lo;
        j = min(j, mvj);          // j >= 0 already
        float cj = (j == 0) ? 0.0f : cum[j - 1];
        float tl = (tgt - cj) / fmaxf(sl[j], 1e-9f);
        tl = fminf(fmaxf(tl, 0.0f), 1.0f);
        float ax = rx[j], ay = ry[j], az = rz[j];
        float prx = ax + tl * (rx[j + 1] - ax);
        float pry = ay + tl * (ry[j + 1] - ay);
        float prz = az + tl * (rz[j + 1] - az);
        size_t po = ((size_t)(n * NB2 + b2) * TT + tid) * 3;
        g_proj[po + 0] = prx;
        g_proj[po + 1] = pry;
        g_proj[po + 2] = prz;
        float dx = px[tid] - prx, dy = py[tid] - pry, dz = pz[tid] - prz;
        dist = sqrtf(dx * dx + dy * dy + dz * dz);
    }
    rd[tid] = dist;
    __syncthreads();
    #pragma unroll
    for (int s = 128; s > 0; s >>= 1) {
        if (tid < s) rd[tid] += rd[tid + s];
        __syncthreads();
    }
    if (tid == 0)
        g_cost[n * NB2 + b2] = sh_has ? rd[0] : BIGF;
}

__global__ __launch_bounds__(128)
void pick_kernel(const float* __restrict__ traj, float* __restrict__ out)
{
    __shared__ float cst[NB2];
    __shared__ int   sh_b, sh_has;
    const int n = blockIdx.x, tid = threadIdx.x;
    if (tid < NB2) cst[tid] = g_cost[n * NB2 + tid];
    __syncthreads();
    if (tid == 0) {
        int best = 0; float bv = cst[0];
        #pragma unroll
        for (int i = 1; i < NB2; ++i)
            if (cst[i] < bv) { bv = cst[i]; best = i; }   // strict < : first-occurrence argmin
        sh_b = best;
        sh_has = (bv < BIGF);
    }
    __syncthreads();
    if (tid < TT) {
        size_t oo = (size_t)(n * TT + tid) * 3;
        if (sh_has) {
            size_t po = ((size_t)(n * NB2 + sh_b) * TT + tid) * 3;
            out[oo + 0] = g_proj[po + 0];
            out[oo + 1] = g_proj[po + 1];
            out[oo + 2] = g_proj[po + 2];
        } else {
            out[oo + 0] = traj[oo + 0];
            out[oo + 1] = traj[oo + 1];
            out[oo + 2] = traj[oo + 2];
        }
    }
}

extern "C" void kernel_launch(void* const* d_in, const int* in_sizes, int n_in,
                              void* d_out, int out_size)
{
    const float*         traj = (const float*)d_in[0];          // [64,128,3]
    const float*         road = (const float*)d_in[1];          // [64,16,256,3]
    const unsigned char* mask = (const unsigned char*)d_in[2];  // [64,16,256] bool/int32
    float* out = (float*)d_out;

    dim3 grid1(NB2, NN);
    arc_branch_kernel<<<grid1, 256>>>(traj, road, mask);
    pick_kernel<<<NN, 128>>>(traj, out);
}

// round 3
// speedup vs baseline: 1.1233x; 1.1233x over previous
#include <cuda_runtime.h>

#define NN   64
#define TT   128
#define NBR  16
#define NB2  32
#define NP   256
#define NS   255
#define BIGF 1e30f
#define FULLMASK 0xFFFFFFFFu

__device__ float g_proj[NN * NB2 * TT * 3];
__device__ float g_cost[NN * NB2];
__device__ int   g_cnt[NN];            // zero-initialized; reset by picker each launch

__global__ __launch_bounds__(256)
void fused_arc_kernel(const float* __restrict__ traj,
                      const float* __restrict__ road,
                      const unsigned char* __restrict__ maskraw,
                      float* __restrict__ out)
{
    __shared__ float rx[NP], ry[NP], rz[NP];
    __shared__ unsigned char rm[NP];
    __shared__ float sl[NP];
    __shared__ float cum[NP];          // inclusive scan of sl
    __shared__ float px[TT], py[TT], pz[TT];
    __shared__ float tcs_s[TT];        // inclusive scan of traj seg len
    __shared__ float wsA[8], wsB[8];   // warp scan totals
    __shared__ float wd[8];            // warp argmin d2
    __shared__ int   wi[8];            // warp argmin idx
    __shared__ int   wm[8];            // warp max valid idx+1
    __shared__ float wsum[8];          // warp dist sums
    __shared__ int   sh_pick;          // 1 if this CTA is the picker
    __shared__ int   sh_b, sh_hasb;    // winning branch, sample-has-branch

    const int tid  = threadIdx.x;
    const int lane = tid & 31;
    const int w    = tid >> 5;
    const int b2   = blockIdx.x;       // 0..31
    const int n    = blockIdx.y;
    const bool bw  = (b2 >= NBR);
    const int b    = bw ? (b2 - NBR) : b2;
    const int src  = bw ? (NP - 1 - tid) : tid;

    // ---- loads
    const float* rp = road + (size_t)((n * NBR + b) * NP) * 3;
    rx[tid] = rp[src * 3 + 0];
    ry[tid] = rp[src * 3 + 1];
    rz[tid] = rp[src * 3 + 2];
    {
        // mask dtype disambiguation: lengths>=2 => element (0,0,1) true.
        // uint8: byte[1]==1; int32 LE: byte[1]==0.
        const bool m32 = (maskraw[1] == 0);
        const size_t e = (size_t)(n * NBR + b) * NP + src;
        rm[tid] = m32 ? (unsigned char)(((const int*)maskraw)[e] != 0)
                      : (unsigned char)(maskraw[e] != 0);
    }
    if (tid < TT) {
        const float* pt = traj + (size_t)(n * TT + tid) * 3;
        px[tid] = pt[0]; py[tid] = pt[1]; pz[tid] = pt[2];
    }
    __syncthreads();                                            // B1

    // ---- segment lengths (masked), traj segment lengths
    float slv = 0.0f;
    bool  smv = false;
    if (tid < NS) {
        smv = (rm[tid] != 0) && (rm[tid + 1] != 0);
        float dx = rx[tid + 1] - rx[tid];
        float dy = ry[tid + 1] - ry[tid];
        float dz = rz[tid + 1] - rz[tid];
        slv = smv ? sqrtf(dx * dx + dy * dy + dz * dz) : 0.0f;
    }
    sl[tid] = slv;

    float tlv = 0.0f;
    if (tid < TT - 1) {
        float dx = px[tid + 1] - px[tid];
        float dy = py[tid + 1] - py[tid];
        float dz = pz[tid + 1] - pz[tid];
        tlv = sqrtf(dx * dx + dy * dy + dz * dz);
    }

    // ---- joint warp-shuffle inclusive scans (sl over 256, traj over first 128)
    float vA = slv, vB = tlv;
    #pragma unroll
    for (int off = 1; off < 32; off <<= 1) {
        float tA = __shfl_up_sync(FULLMASK, vA, off);
        float tB = __shfl_up_sync(FULLMASK, vB, off);
        if (lane >= off) { vA += tA; vB += tB; }
    }
    if (lane == 31) { wsA[w] = vA; wsB[w] = vB; }
    __syncthreads();                                            // B2
    float offA = 0.0f, offB = 0.0f;
    #pragma unroll
    for (int k = 0; k < 8; ++k) {
        if (k < w) { offA += wsA[k]; offB += wsB[k]; }
    }
    cum[tid] = vA + offA;
    if (tid < TT) tcs_s[tid] = vB + offB;

    // ---- p0 projection d2 per segment (no barrier needed: uses regs + stable smem)
    const float p0x = px[0], p0y = py[0], p0z = pz[0];
    float d2 = BIGF;
    float ax0 = 0, ay0 = 0, az0 = 0, svx0 = 0, svy0 = 0, svz0 = 0;
    if (tid < NS) {
        ax0 = rx[tid];  ay0 = ry[tid];  az0 = rz[tid];
        svx0 = rx[tid + 1] - ax0; svy0 = ry[tid + 1] - ay0; svz0 = rz[tid + 1] - az0;
        float svdot = fmaxf(svx0 * svx0 + svy0 * svy0 + svz0 * svz0, 1e-12f);
        float t0 = ((p0x - ax0) * svx0 + (p0y - ay0) * svy0 + (p0z - az0) * svz0) / svdot;
        t0 = fminf(fmaxf(t0, 0.0f), 1.0f);
        float qx = ax0 + t0 * svx0, qy = ay0 + t0 * svy0, qz = az0 + t0 * svz0;
        float ex = p0x - qx, ey = p0y - qy, ez = p0z - qz;
        d2 = smv ? (ex * ex + ey * ey + ez * ez) : BIGF;
    }
    // warp argmin (first-occurrence tie-break) + warp max valid
    float bd = d2; int bi = tid;
    int mv = (tid < NS && smv) ? (tid + 1) : 0;
    #pragma unroll
    for (int off = 16; off > 0; off >>= 1) {
        float od = __shfl_xor_sync(FULLMASK, bd, off);
        int   oi = __shfl_xor_sync(FULLMASK, bi, off);
        int   om = __shfl_xor_sync(FULLMASK, mv, off);
        if (od < bd || (od == bd && oi < bi)) { bd = od; bi = oi; }
        mv = max(mv, om);
    }
    if (lane == 0) { wd[w] = bd; wi[w] = bi; wm[w] = mv; }
    __syncthreads();                                            // B3 (also publishes cum/tcs_s)

    // per-thread serial combine (8 smem broadcast reads, warps in index order)
    float fbd = wd[0]; int fbi = wi[0]; int fmv = wm[0];
    #pragma unroll
    for (int k = 1; k < 8; ++k) {
        float od = wd[k];
        if (od < fbd) { fbd = od; fbi = wi[k]; }
        fmv = max(fmv, wm[k]);
    }
    const int  seg0 = fbi;              // <=254 (255 has BIG, loses ties to lower idx)
    const int  mvj  = (fmv > 0) ? (fmv - 1) : 0;
    const bool has  = (fmv > 0);

    // entry arclength at seg0 (recomputed by every thread; smem broadcasts)
    float entry, total;
    {
        int k = seg0;
        float ax = rx[k], ay = ry[k], az = rz[k];
        float svx = rx[k + 1] - ax, svy = ry[k + 1] - ay, svz = rz[k + 1] - az;
        float svdot = fmaxf(svx * svx + svy * svy + svz * svz, 1e-12f);
        float t0 = ((p0x - ax) * svx + (p0y - ay) * svy + (p0z - az) * svz) / svdot;
        t0 = fminf(fmaxf(t0, 0.0f), 1.0f);
        float c0 = (k == 0) ? 0.0f : cum[k - 1];
        entry = c0 + t0 * sl[k];
        total = cum[NP - 1];
    }

    // ---- walk trajectory along arc, project, write per-branch proj, distance
    float dist = 0.0f;
    if (tid < TT) {
        float tcv = (tid == 0) ? 0.0f : tcs_s[tid - 1];
        float tgt = fmaxf(fminf(entry + tcv, total), 0.0f);
        int lo = 0, hi = NP - 1;
        #pragma unroll
        for (int it = 0; it < 8; ++it) {
            if (lo < hi) {
                int mid = (lo + hi + 1) >> 1;
                if (cum[mid - 1] <= tgt) lo = mid; else hi = mid - 1;
            }
        }
        int j = min(lo, mvj);
        float cj = (j == 0) ? 0.0f : cum[j - 1];
        float tl = fminf(fmaxf((tgt - cj) / fmaxf(sl[j], 1e-9f), 0.0f), 1.0f);
        float ax = rx[j], ay = ry[j], az = rz[j];
        float prx = ax + tl * (rx[j + 1] - ax);
        float pry = ay + tl * (ry[j + 1] - ay);
        float prz = az + tl * (rz[j + 1] - az);
        size_t po = ((size_t)(n * NB2 + b2) * TT + tid) * 3;
        g_proj[po + 0] = prx;
        g_proj[po + 1] = pry;
        g_proj[po + 2] = prz;
        float dx = px[tid] - prx, dy = py[tid] - pry, dz = pz[tid] - prz;
        dist = sqrtf(dx * dx + dy * dy + dz * dz);
    }
    __threadfence();   // release: make this thread's g_proj stores device-visible

    // warp sum + cross-warp sum
    #pragma unroll
    for (int off = 16; off > 0; off >>= 1)
        dist += __shfl_xor_sync(FULLMASK, dist, off);
    if (lane == 0) wsum[w] = dist;
    __syncthreads();                                            // B4

    if (tid == 0) {
        float c = 0.0f;
        #pragma unroll
        for (int k = 0; k < 8; ++k) c += wsum[k];
        g_cost[n * NB2 + b2] = has ? c : BIGF;
        __threadfence();                                        // release cost
        int old = atomicAdd(&g_cnt[n], 1);
        sh_pick = (old == NB2 - 1);
    }
    __syncthreads();                                            // B5

    if (!sh_pick) return;

    // ---- this CTA is last for sample n: do the 32-way pick + gather
    __threadfence();   // acquire
    if (w == 0) {
        float cv = __ldcg(&g_cost[n * NB2 + lane]);
        float pbd = cv; int pbi = lane;
        #pragma unroll
        for (int off = 16; off > 0; off >>= 1) {
            float od = __shfl_xor_sync(FULLMASK, pbd, off);
            int   oi = __shfl_xor_sync(FULLMASK, pbi, off);
            if (od < pbd || (od == pbd && oi < pbi)) { pbd = od; pbi = oi; }
        }
        if (lane == 0) { sh_b = pbi; sh_hasb = (pbd < BIGF); }
    }
    __syncthreads();                                            // B6

    if (tid < TT) {
        size_t oo = (size_t)(n * TT + tid) * 3;
        if (sh_hasb) {
            size_t po = ((size_t)(n * NB2 + sh_b) * TT + tid) * 3;
            out[oo + 0] = __ldcg(&g_proj[po + 0]);
            out[oo + 1] = __ldcg(&g_proj[po + 1]);
            out[oo + 2] = __ldcg(&g_proj[po + 2]);
        } else {
            out[oo + 0] = px[tid];
            out[oo + 1] = py[tid];
            out[oo + 2] = pz[tid];
        }
    }
    if (tid == 0) g_cnt[n] = 0;        // reset for next graph replay
}

extern "C" void kernel_launch(void* const* d_in, const int* in_sizes, int n_in,
                              void* d_out, int out_size)
{
    const float*         traj = (const float*)d_in[0];
    const float*         road = (const float*)d_in[1];
    const unsigned char* mask = (const unsigned char*)d_in[2];
    float* out = (float*)d_out;

    dim3 grid(NB2, NN);
    fused_arc_kernel<<<grid, 256>>>(traj, road, mask, out);
}

// round 4
// speedup vs baseline: 1.3185x; 1.1737x over previous
#include <cuda_runtime.h>

#define NN   64
#define TT   128
#define NBR  16
#define NB2  32
#define NP   256
#define NS   255
#define BIGF 1e30f
#define FULLMASK 0xFFFFFFFFu

__device__ float g_proj[NN * NB2 * TT * 3];
__device__ float g_cost[NN * NB2];
__device__ int   g_cnt[NN];          // zero-init; picker resets each launch

__global__ __launch_bounds__(256)
void fused_arc_kernel(const float* __restrict__ traj,
                      const float* __restrict__ road,
                      const unsigned char* __restrict__ maskraw,
                      float* __restrict__ out)
{
    __shared__ float rx[NP], ry[NP], rz[NP];
    __shared__ unsigned char rm[NP];
    __shared__ float sl[NP];           // fwd seg len (0 invalid); sl[255]=0
    __shared__ float cum[NP];          // inclusive scan of sl  (cum_s_fw(i)= i? cum[i-1]:0)
    __shared__ float cumB[NP];         // cumB[t] = cum_s_bw(t+1)
    __shared__ float px[TT], py[TT], pz[TT];
    __shared__ float tcs_s[TT];        // inclusive scan of traj seg len
    __shared__ float wsA[8], wsB[8];
    __shared__ float wd[8];            // warp argmin d2
    __shared__ int   wi[8];            // warp argmin idx
    __shared__ int   wmx[8], wmn[8];   // warp max(valid+1), min(valid idx | 255)
    __shared__ float wsum[8];
    __shared__ int   sh_pick, sh_b, sh_hasb;

    const int tid  = threadIdx.x;
    const int lane = tid & 31;
    const int w    = tid >> 5;
    const int b    = blockIdx.x;       // 0..15 (undirected branch)
    const int n    = blockIdx.y;

    // ---- loads (natural order; bwd derived analytically)
    const float* rp = road + (size_t)((n * NBR + b) * NP) * 3;
    rx[tid] = rp[tid * 3 + 0];
    ry[tid] = rp[tid * 3 + 1];
    rz[tid] = rp[tid * 3 + 2];
    // mask dtype: lengths>=2 => element (0,0,1) true. int32 LE => byte[1]==0.
    if (maskraw[1] == 0) {
        rm[tid] = (unsigned char)(((const int*)maskraw)[(size_t)(n * NBR + b) * NP + tid] != 0);
    } else {
        rm[tid] = (unsigned char)(maskraw[(size_t)(n * NBR + b) * NP + tid] != 0);
    }
    if (tid < TT) {
        const float* pt = traj + (size_t)(n * TT + tid) * 3;
        px[tid] = pt[0]; py[tid] = pt[1]; pz[tid] = pt[2];
    }
    __syncthreads();                                            // B1

    // ---- fwd segment lengths (masked), traj segment lengths
    float slv = 0.0f;
    bool  smv = false;
    if (tid < NS) {
        smv = (rm[tid] != 0) && (rm[tid + 1] != 0);
        float dx = rx[tid + 1] - rx[tid];
        float dy = ry[tid + 1] - ry[tid];
        float dz = rz[tid + 1] - rz[tid];
        slv = smv ? sqrtf(dx * dx + dy * dy + dz * dz) : 0.0f;
    }
    sl[tid] = slv;

    float tlv = 0.0f;
    if (tid < TT - 1) {
        float dx = px[tid + 1] - px[tid];
        float dy = py[tid + 1] - py[tid];
        float dz = pz[tid + 1] - pz[tid];
        tlv = sqrtf(dx * dx + dy * dy + dz * dz);
    }

    // ---- joint warp-shuffle inclusive scans
    float vA = slv, vB = tlv;
    #pragma unroll
    for (int off = 1; off < 32; off <<= 1) {
        float tA = __shfl_up_sync(FULLMASK, vA, off);
        float tB = __shfl_up_sync(FULLMASK, vB, off);
        if (lane >= off) { vA += tA; vB += tB; }
    }
    if (lane == 31) { wsA[w] = vA; wsB[w] = vB; }
    __syncthreads();                                            // B2
    float offA = 0.0f, offB = 0.0f;
    #pragma unroll
    for (int k = 0; k < 8; ++k) {
        if (k < w) { offA += wsA[k]; offB += wsB[k]; }
    }
    cum[tid] = vA + offA;
    if (tid < TT) tcs_s[tid] = vB + offB;

    // ---- p0 projection d2 per fwd segment (same segment set serves bwd)
    const float p0x = px[0], p0y = py[0], p0z = pz[0];
    float d2 = BIGF;
    if (tid < NS) {
        float ax = rx[tid], ay = ry[tid], az = rz[tid];
        float svx = rx[tid + 1] - ax, svy = ry[tid + 1] - ay, svz = rz[tid + 1] - az;
        float svdot = fmaxf(svx * svx + svy * svy + svz * svz, 1e-12f);
        float t0 = ((p0x - ax) * svx + (p0y - ay) * svy + (p0z - az) * svz) / svdot;
        t0 = fminf(fmaxf(t0, 0.0f), 1.0f);
        float qx = ax + t0 * svx, qy = ay + t0 * svy, qz = az + t0 * svz;
        float ex = p0x - qx, ey = p0y - qy, ez = p0z - qz;
        d2 = smv ? (ex * ex + ey * ey + ez * ez) : BIGF;
    }
    // warp argmin (first-occurrence) + max valid (+1) + min valid (sentinel 255)
    float bd = d2; int bi = tid;
    int mx = (tid < NS && smv) ? (tid + 1) : 0;
    int mn = (tid < NS && smv) ? tid : NS;
    #pragma unroll
    for (int off = 16; off > 0; off >>= 1) {
        float od = __shfl_xor_sync(FULLMASK, bd, off);
        int   oi = __shfl_xor_sync(FULLMASK, bi, off);
        int   ox = __shfl_xor_sync(FULLMASK, mx, off);
        int   on = __shfl_xor_sync(FULLMASK, mn, off);
        if (od < bd || (od == bd && oi < bi)) { bd = od; bi = oi; }
        mx = max(mx, ox);
        mn = min(mn, on);
    }
    if (lane == 0) { wd[w] = bd; wi[w] = bi; wmx[w] = mx; wmn[w] = mn; }
    __syncthreads();                                            // B3 (publishes cum/tcs_s too)

    float fbd = wd[0]; int fbi = wi[0]; int fmx = wmx[0]; int fmn = wmn[0];
    #pragma unroll
    for (int k = 1; k < 8; ++k) {
        float od = wd[k];
        if (od < fbd) { fbd = od; fbi = wi[k]; }
        fmx = max(fmx, wmx[k]);
        fmn = min(fmn, wmn[k]);
    }
    const int  seg0 = fbi;
    const bool has  = (fmx > 0);
    const int  mvjF = has ? (fmx - 1) : 0;       // max valid fwd seg
    const int  mvjB = has ? (NS - 1 - fmn) : 0;  // 254 - min valid fwd seg

    const float total = cum[NP - 1];
    float entryF;
    {
        int k = seg0;
        float ax = rx[k], ay = ry[k], az = rz[k];
        float svx = rx[k + 1] - ax, svy = ry[k + 1] - ay, svz = rz[k + 1] - az;
        float svdot = fmaxf(svx * svx + svy * svy + svz * svz, 1e-12f);
        float t0 = ((p0x - ax) * svx + (p0y - ay) * svy + (p0z - az) * svz) / svdot;
        t0 = fminf(fmaxf(t0, 0.0f), 1.0f);
        float c0 = (k == 0) ? 0.0f : cum[k - 1];
        entryF = c0 + t0 * sl[k];
    }
    const float entryB = total - entryF;

    // cumB[t] = cum_s_bw(t+1) = total - cum_s_fw(254-t)
    if (tid < NS)
        cumB[tid] = (tid == NS - 1) ? total : (total - cum[NS - 2 - tid]);
    __syncthreads();                                            // B3b

    // ---- walks: warps 0-3 forward branch (b2=b), warps 4-7 backward (b2=b+16)
    const bool  isB = (tid >= TT);
    const int   t   = tid & (TT - 1);
    const int   b2  = isB ? (b + NBR) : b;
    const float entry = isB ? entryB : entryF;
    const int   mvj   = isB ? mvjB : mvjF;
    const float* cs   = isB ? cumB : cum;

    float tcv = (t == 0) ? 0.0f : tcs_s[t - 1];
    float tgt = fmaxf(fminf(entry + tcv, total), 0.0f);
    int lo = 0, hi = NP - 1;
    #pragma unroll
    for (int it = 0; it < 8; ++it) {
        if (lo < hi) {
            int mid = (lo + hi + 1) >> 1;
            if (cs[mid - 1] <= tgt) lo = mid; else hi = mid - 1;
        }
    }
    int j = min(lo, mvj);
    float cj  = (j == 0) ? 0.0f : cs[j - 1];
    float slj = isB ? sl[NS - 1 - j] : sl[j];
    float tl  = fminf(fmaxf((tgt - cj) / fmaxf(slj, 1e-9f), 0.0f), 1.0f);
    float prx, pry, prz;
    if (isB) {
        int r = NP - 1 - j;                 // a_bw[j] = P[255-j], next = P[254-j]
        float ax = rx[r], ay = ry[r], az = rz[r];
        prx = ax + tl * (rx[r - 1] - ax);
        pry = ay + tl * (ry[r - 1] - ay);
        prz = az + tl * (rz[r - 1] - az);
    } else {
        float ax = rx[j], ay = ry[j], az = rz[j];
        prx = ax + tl * (rx[j + 1] - ax);
        pry = ay + tl * (ry[j + 1] - ay);
        prz = az + tl * (rz[j + 1] - az);
    }
    {
        size_t po = ((size_t)(n * NB2 + b2) * TT + t) * 3;
        g_proj[po + 0] = prx;
        g_proj[po + 1] = pry;
        g_proj[po + 2] = prz;
    }
    float dx = px[t] - prx, dy = py[t] - pry, dz = pz[t] - prz;
    float dist = sqrtf(dx * dx + dy * dy + dz * dz);

    // warp sum; warps 0-3 => fwd cost, 4-7 => bwd cost
    #pragma unroll
    for (int off = 16; off > 0; off >>= 1)
        dist += __shfl_xor_sync(FULLMASK, dist, off);
    if (lane == 0) wsum[w] = dist;
    __syncthreads();                                            // B4

    if (tid == 0) {
        float cf = wsum[0] + wsum[1] + wsum[2] + wsum[3];
        float cb = wsum[4] + wsum[5] + wsum[6] + wsum[7];
        g_cost[n * NB2 + b]       = has ? cf : BIGF;
        g_cost[n * NB2 + b + NBR] = has ? cb : BIGF;
        __threadfence();                       // release g_proj + g_cost
        int old = atomicAdd(&g_cnt[n], 1);
        sh_pick = (old == NBR - 1);
    }
    __syncthreads();                                            // B5

    if (!sh_pick) return;

    // ---- picker CTA for sample n: 32-way argmin + gather
    __threadfence();                           // acquire
    if (w == 0) {
        float cv = __ldcg(&g_cost[n * NB2 + lane]);
        float pbd = cv; int pbi = lane;
        #pragma unroll
        for (int off = 16; off > 0; off >>= 1) {
            float od = __shfl_xor_sync(FULLMASK, pbd, off);
            int   oi = __shfl_xor_sync(FULLMASK, pbi, off);
            if (od < pbd || (od == pbd && oi < pbi)) { pbd = od; pbi = oi; }
        }
        if (lane == 0) { sh_b = pbi; sh_hasb = (pbd < BIGF); }
    }
    __syncthreads();                                            // B6

    if (tid < TT) {
        size_t oo = (size_t)(n * TT + tid) * 3;
        if (sh_hasb) {
            size_t po = ((size_t)(n * NB2 + sh_b) * TT + tid) * 3;
            out[oo + 0] = __ldcg(&g_proj[po + 0]);
            out[oo + 1] = __ldcg(&g_proj[po + 1]);
            out[oo + 2] = __ldcg(&g_proj[po + 2]);
        } else {
            out[oo + 0] = px[tid];
            out[oo + 1] = py[tid];
            out[oo + 2] = pz[tid];
        }
    }
    if (tid == 0) g_cnt[n] = 0;                // reset for next graph replay
}

extern "C" void kernel_launch(void* const* d_in, const int* in_sizes, int n_in,
                              void* d_out, int out_size)
{
    const float*         traj = (const float*)d_in[0];
    const float*         road = (const float*)d_in[1];
    const unsigned char* mask = (const unsigned char*)d_in[2];
    float* out = (float*)d_out;

    dim3 grid(NBR, NN);
    fused_arc_kernel<<<grid, 256>>>(traj, road, mask, out);
}

// round 5
// speedup vs baseline: 1.4510x; 1.1005x over previous
#include <cuda_runtime.h>

#define NN   64
#define TT   128
#define NBR  16
#define NB2  32
#define NP   256
#define NS   255
#define BIGF 1e30f
#define FULLMASK 0xFFFFFFFFu

__device__ float g_proj[NN * NB2 * TT * 3];
__device__ float g_cost[NN * NB2];
__device__ int   g_cnt[NN];          // zero-init; picker resets each launch

__global__ __launch_bounds__(256)
void fused_arc_kernel(const float* __restrict__ traj,
                      const float* __restrict__ road,
                      const unsigned char* __restrict__ maskraw,
                      float* __restrict__ out)
{
    __shared__ float rx[NP], ry[NP], rz[NP];
    __shared__ unsigned char rm[NP];
    __shared__ float sl[NP];           // fwd seg len (0 invalid); sl[255]=0
    __shared__ float cum[NP];          // inclusive scan of sl
    __shared__ float cumB[NP];         // cumB[t] = cum_s_bw(t+1)
    __shared__ float px[TT], py[TT], pz[TT];
    __shared__ float tcs_s[TT];        // inclusive scan of traj seg len
    __shared__ float wsA[8], wsB[8];
    __shared__ float wsum[8];
    __shared__ unsigned long long s_key;   // (d2bits<<32)|segidx : exact argmin
    __shared__ int   s_mn, s_mx;           // min valid idx / (max valid idx + 1)
    __shared__ int   sh_pick, sh_b, sh_hasb;

    const int tid  = threadIdx.x;
    const int lane = tid & 31;
    const int w    = tid >> 5;
    const int b    = blockIdx.x;       // undirected branch 0..15
    const int n    = blockIdx.y;

    if (tid == 0) {
        s_key = ~0ull;
        s_mn  = NS;
        s_mx  = 0;
    }

    // ---- loads (natural order; bwd derived analytically)
    const float* rp = road + (size_t)((n * NBR + b) * NP) * 3;
    rx[tid] = rp[tid * 3 + 0];
    ry[tid] = rp[tid * 3 + 1];
    rz[tid] = rp[tid * 3 + 2];
    // mask dtype: lengths>=2 => element (0,0,1) true. int32 LE => byte[1]==0.
    if (maskraw[1] == 0) {
        rm[tid] = (unsigned char)(((const int*)maskraw)[(size_t)(n * NBR + b) * NP + tid] != 0);
    } else {
        rm[tid] = (unsigned char)(maskraw[(size_t)(n * NBR + b) * NP + tid] != 0);
    }
    if (tid < TT) {
        const float* pt = traj + (size_t)(n * TT + tid) * 3;
        px[tid] = pt[0]; py[tid] = pt[1]; pz[tid] = pt[2];
    }
    __syncthreads();                                            // B1

    // ---- fwd segment lengths (masked), traj segment lengths
    float slv = 0.0f;
    bool  smv = false;
    if (tid < NS) {
        smv = (rm[tid] != 0) && (rm[tid + 1] != 0);
        float dx = rx[tid + 1] - rx[tid];
        float dy = ry[tid + 1] - ry[tid];
        float dz = rz[tid + 1] - rz[tid];
        slv = smv ? sqrtf(dx * dx + dy * dy + dz * dz) : 0.0f;
    }
    sl[tid] = slv;

    float tlv = 0.0f;
    if (tid < TT - 1) {
        float dx = px[tid + 1] - px[tid];
        float dy = py[tid + 1] - py[tid];
        float dz = pz[tid + 1] - pz[tid];
        tlv = sqrtf(dx * dx + dy * dy + dz * dz);
    }

    // ---- joint warp-shuffle inclusive scans
    float vA = slv, vB = tlv;
    #pragma unroll
    for (int off = 1; off < 32; off <<= 1) {
        float tA = __shfl_up_sync(FULLMASK, vA, off);
        float tB = __shfl_up_sync(FULLMASK, vB, off);
        if (lane >= off) { vA += tA; vB += tB; }
    }
    if (lane == 31) { wsA[w] = vA; wsB[w] = vB; }
    __syncthreads();                                            // B2
    {
        float offA = 0.0f, offB = 0.0f;
        #pragma unroll
        for (int k = 0; k < 7; ++k) {
            if (k < w) { offA += wsA[k]; offB += wsB[k]; }
        }
        cum[tid] = vA + offA;
        if (tid < TT) tcs_s[tid] = vB + offB;
    }

    // ---- p0 projection d2 per fwd segment; CTA argmin via redux+ballot+smem atomic
    const float p0x = px[0], p0y = py[0], p0z = pz[0];
    float d2 = BIGF;
    if (tid < NS && smv) {
        float ax = rx[tid], ay = ry[tid], az = rz[tid];
        float svx = rx[tid + 1] - ax, svy = ry[tid + 1] - ay, svz = rz[tid + 1] - az;
        float svdot = fmaxf(svx * svx + svy * svy + svz * svz, 1e-12f);
        float t0 = ((p0x - ax) * svx + (p0y - ay) * svy + (p0z - az) * svz) / svdot;
        t0 = fminf(fmaxf(t0, 0.0f), 1.0f);
        float qx = ax + t0 * svx, qy = ay + t0 * svy, qz = az + t0 * svz;
        float ex = p0x - qx, ey = p0y - qy, ez = p0z - qz;
        d2 = ex * ex + ey * ey + ez * ez;
    }
    {
        unsigned bits = __float_as_uint(d2);            // d2>=0 => order-preserving
        unsigned wmin = __reduce_min_sync(FULLMASK, bits);
        unsigned ball = __ballot_sync(FULLMASK, bits == wmin);
        if (lane == 0) {
            int idx = (w << 5) + (__ffs(ball) - 1);     // first-occurrence in warp
            atomicMin(&s_key, ((unsigned long long)wmin << 32) | (unsigned)idx);
        }
        unsigned vb = __ballot_sync(FULLMASK, smv);
        if (lane == 0 && vb) {
            atomicMin(&s_mn, (w << 5) + (__ffs(vb) - 1));
            atomicMax(&s_mx, (w << 5) + (32 - __clz(vb)));
        }
    }
    __syncthreads();                                            // B3 (cum/tcs_s/atomics done)

    const int  seg0 = (int)(unsigned)(s_key & 0xFFFFFFFFull);
    const int  fmx  = s_mx;
    const int  fmn  = s_mn;
    const bool has  = (fmx > 0);
    const int  mvjF = has ? (fmx - 1) : 0;
    const int  mvjB = has ? (NS - 1 - fmn) : 0;

    const float total = cum[NP - 1];
    float entryF;
    {
        int k = seg0;
        float ax = rx[k], ay = ry[k], az = rz[k];
        float svx = rx[k + 1] - ax, svy = ry[k + 1] - ay, svz = rz[k + 1] - az;
        float svdot = fmaxf(svx * svx + svy * svy + svz * svz, 1e-12f);
        float t0 = ((p0x - ax) * svx + (p0y - ay) * svy + (p0z - az) * svz) / svdot;
        t0 = fminf(fmaxf(t0, 0.0f), 1.0f);
        float c0 = (k == 0) ? 0.0f : cum[k - 1];
        entryF = c0 + t0 * sl[k];
    }
    const float entryB = total - entryF;

    // cumB[t] = cum_s_bw(t+1) = total - cum_s_fw(254-t)
    if (tid < NS)
        cumB[tid] = (tid == NS - 1) ? total : (total - cum[NS - 2 - tid]);
    __syncthreads();                                            // B3b

    // ---- walks: warps 0-3 fwd (b2=b), warps 4-7 bwd (b2=b+16)
    const bool  isB = (tid >= TT);
    const int   t   = tid & (TT - 1);
    const int   b2  = isB ? (b + NBR) : b;
    const float entry = isB ? entryB : entryF;
    const int   mvj   = isB ? mvjB : mvjF;
    const float* cs   = isB ? cumB : cum;

    float tcv = (t == 0) ? 0.0f : tcs_s[t - 1];
    float tgt = fmaxf(fminf(entry + tcv, total), 0.0f);
    // branchless: largest j in [0,255] with cum_s(j) <= tgt  (cum_s(j)=cs[j-1], cum_s(0)=0)
    int j = 0;
    #pragma unroll
    for (int step = 128; step > 0; step >>= 1) {
        int nj = j + step;                  // nj <= 255 always
        if (cs[nj - 1] <= tgt) j = nj;
    }
    j = min(j, mvj);
    float cj  = (j == 0) ? 0.0f : cs[j - 1];
    float slj = isB ? sl[NS - 1 - j] : sl[j];
    float tl  = fminf(fmaxf((tgt - cj) / fmaxf(slj, 1e-9f), 0.0f), 1.0f);
    float prx, pry, prz;
    if (isB) {
        int r = NP - 1 - j;                 // a_bw[j] = P[255-j], next = P[254-j]
        float ax = rx[r], ay = ry[r], az = rz[r];
        prx = ax + tl * (rx[r - 1] - ax);
        pry = ay + tl * (ry[r - 1] - ay);
        prz = az + tl * (rz[r - 1] - az);
    } else {
        float ax = rx[j], ay = ry[j], az = rz[j];
        prx = ax + tl * (rx[j + 1] - ax);
        pry = ay + tl * (ry[j + 1] - ay);
        prz = az + tl * (rz[j + 1] - az);
    }
    {
        size_t po = ((size_t)(n * NB2 + b2) * TT + t) * 3;
        g_proj[po + 0] = prx;
        g_proj[po + 1] = pry;
        g_proj[po + 2] = prz;
    }
    float dx = px[t] - prx, dy = py[t] - pry, dz = pz[t] - prz;
    float dist = sqrtf(dx * dx + dy * dy + dz * dz);

    // deterministic dist sums (warp shfl + fixed-order combine)
    #pragma unroll
    for (int off = 16; off > 0; off >>= 1)
        dist += __shfl_xor_sync(FULLMASK, dist, off);
    if (lane == 0) wsum[w] = dist;
    __syncthreads();                                            // B4

    if (tid == 0) {
        float cf = wsum[0] + wsum[1] + wsum[2] + wsum[3];
        float cb = wsum[4] + wsum[5] + wsum[6] + wsum[7];
        g_cost[n * NB2 + b]       = has ? cf : BIGF;
        g_cost[n * NB2 + b + NBR] = has ? cb : BIGF;
        __threadfence();                       // release g_proj + g_cost
        int old = atomicAdd(&g_cnt[n], 1);
        sh_pick = (old == NBR - 1);
    }
    __syncthreads();                                            // B5

    if (!sh_pick) return;

    // ---- picker CTA for sample n: 32-way argmin + gather
    __threadfence();                           // acquire
    if (w == 0) {
        float cv = __ldcg(&g_cost[n * NB2 + lane]);
        float pbd = cv; int pbi = lane;
        #pragma unroll
        for (int off = 16; off > 0; off >>= 1) {
            float od = __shfl_xor_sync(FULLMASK, pbd, off);
            int   oi = __shfl_xor_sync(FULLMASK, pbi, off);
            if (od < pbd || (od == pbd && oi < pbi)) { pbd = od; pbi = oi; }
        }
        if (lane == 0) { sh_b = pbi; sh_hasb = (pbd < BIGF); }
    }
    __syncthreads();                                            // B6

    if (tid < TT) {
        size_t oo = (size_t)(n * TT + tid) * 3;
        if (sh_hasb) {
            size_t po = ((size_t)(n * NB2 + sh_b) * TT + tid) * 3;
            out[oo + 0] = __ldcg(&g_proj[po + 0]);
            out[oo + 1] = __ldcg(&g_proj[po + 1]);
            out[oo + 2] = __ldcg(&g_proj[po + 2]);
        } else {
            out[oo + 0] = px[tid];
            out[oo + 1] = py[tid];
            out[oo + 2] = pz[tid];
        }
    }
    if (tid == 0) g_cnt[n] = 0;                // reset for next graph replay
}

extern "C" void kernel_launch(void* const* d_in, const int* in_sizes, int n_in,
                              void* d_out, int out_size)
{
    const float*         traj = (const float*)d_in[0];
    const float*         road = (const float*)d_in[1];
    const unsigned char* mask = (const unsigned char*)d_in[2];
    float* out = (float*)d_out;

    dim3 grid(NBR, NN);
    fused_arc_kernel<<<grid, 256>>>(traj, road, mask, out);
}

// round 6
// speedup vs baseline: 1.4837x; 1.0226x over previous
#include <cuda_runtime.h>

#define NN   64
#define TT   128
#define NBR  16
#define NB2  32
#define NP   256
#define NS   255
#define BIGF 1e30f
#define FULLMASK 0xFFFFFFFFu

__device__ float g_proj[NN * NB2 * TT * 3];
__device__ float g_cost[NN * NB2];
__device__ int   g_cnt[NN];          // zero-init; picker resets each launch

__global__ __launch_bounds__(256)
void fused_arc_kernel(const float* __restrict__ traj,
                      const float* __restrict__ road,
                      const unsigned char* __restrict__ maskraw,
                      float* __restrict__ out)
{
    __shared__ float rx[NP], ry[NP], rz[NP];
    __shared__ unsigned char rm[NP];
    __shared__ float sl[NP];           // fwd seg len (0 invalid); sl[255]=0
    __shared__ float cum[NP];          // inclusive scan of sl; cum_s(i)= i? cum[i-1]:0
    __shared__ float px[TT], py[TT], pz[TT];
    __shared__ float tcs_s[TT];        // inclusive scan of traj seg len
    __shared__ float wsA[8], wsB[8];
    __shared__ float wsum[8];
    __shared__ unsigned long long s_key;   // (d2bits<<32)|segidx : exact argmin
    __shared__ int   s_mn, s_mx;
    __shared__ int   sh_pick, sh_b, sh_hasb;

    const int tid  = threadIdx.x;
    const int lane = tid & 31;
    const int w    = tid >> 5;
    const int b    = blockIdx.x;       // undirected branch 0..15
    const int n    = blockIdx.y;

    if (tid == 0) {
        s_key = ~0ull;
        s_mn  = NS;
        s_mx  = 0;
    }

    // ---- loads
    const float* rp = road + (size_t)((n * NBR + b) * NP) * 3;
    rx[tid] = rp[tid * 3 + 0];
    ry[tid] = rp[tid * 3 + 1];
    rz[tid] = rp[tid * 3 + 2];
    // mask dtype: lengths>=2 => element (0,0,1) true. int32 LE => byte[1]==0.
    if (maskraw[1] == 0) {
        rm[tid] = (unsigned char)(((const int*)maskraw)[(size_t)(n * NBR + b) * NP + tid] != 0);
    } else {
        rm[tid] = (unsigned char)(maskraw[(size_t)(n * NBR + b) * NP + tid] != 0);
    }
    if (tid < TT) {
        const float* pt = traj + (size_t)(n * TT + tid) * 3;
        px[tid] = pt[0]; py[tid] = pt[1]; pz[tid] = pt[2];
    }
    __syncthreads();                                            // B1

    // ---- fwd segment lengths (masked), traj segment lengths
    float slv = 0.0f;
    bool  smv = false;
    if (tid < NS) {
        smv = (rm[tid] != 0) && (rm[tid + 1] != 0);
        float dx = rx[tid + 1] - rx[tid];
        float dy = ry[tid + 1] - ry[tid];
        float dz = rz[tid + 1] - rz[tid];
        slv = smv ? sqrtf(dx * dx + dy * dy + dz * dz) : 0.0f;
    }
    sl[tid] = slv;

    float tlv = 0.0f;
    if (tid < TT - 1) {
        float dx = px[tid + 1] - px[tid];
        float dy = py[tid + 1] - py[tid];
        float dz = pz[tid + 1] - pz[tid];
        tlv = sqrtf(dx * dx + dy * dy + dz * dz);
    }

    // ---- joint warp-shuffle inclusive scans
    float vA = slv, vB = tlv;
    #pragma unroll
    for (int off = 1; off < 32; off <<= 1) {
        float tA = __shfl_up_sync(FULLMASK, vA, off);
        float tB = __shfl_up_sync(FULLMASK, vB, off);
        if (lane >= off) { vA += tA; vB += tB; }
    }
    if (lane == 31) { wsA[w] = vA; wsB[w] = vB; }
    __syncthreads();                                            // B2
    {
        float offA = 0.0f, offB = 0.0f;
        #pragma unroll
        for (int k = 0; k < 7; ++k) {
            if (k < w) { offA += wsA[k]; offB += wsB[k]; }
        }
        cum[tid] = vA + offA;
        if (tid < TT) tcs_s[tid] = vB + offB;
    }

    // ---- p0 projection d2 per fwd segment; CTA argmin via redux+ballot+smem atomic
    const float p0x = px[0], p0y = py[0], p0z = pz[0];
    float d2 = BIGF;
    if (tid < NS && smv) {
        float ax = rx[tid], ay = ry[tid], az = rz[tid];
        float svx = rx[tid + 1] - ax, svy = ry[tid + 1] - ay, svz = rz[tid + 1] - az;
        float svdot = fmaxf(svx * svx + svy * svy + svz * svz, 1e-12f);
        float t0 = ((p0x - ax) * svx + (p0y - ay) * svy + (p0z - az) * svz) / svdot;
        t0 = fminf(fmaxf(t0, 0.0f), 1.0f);
        float qx = ax + t0 * svx, qy = ay + t0 * svy, qz = az + t0 * svz;
        float ex = p0x - qx, ey = p0y - qy, ez = p0z - qz;
        d2 = ex * ex + ey * ey + ez * ez;
    }
    {
        unsigned bits = __float_as_uint(d2);            // d2>=0 => order-preserving
        unsigned wmin = __reduce_min_sync(FULLMASK, bits);
        unsigned ball = __ballot_sync(FULLMASK, bits == wmin);
        if (lane == 0) {
            int idx = (w << 5) + (__ffs(ball) - 1);
            atomicMin(&s_key, ((unsigned long long)wmin << 32) | (unsigned)idx);
        }
        unsigned vb = __ballot_sync(FULLMASK, smv);
        if (lane == 0 && vb) {
            atomicMin(&s_mn, (w << 5) + (__ffs(vb) - 1));
            atomicMax(&s_mx, (w << 5) + (32 - __clz(vb)));
        }
    }
    __syncthreads();                                            // B3

    const int  seg0 = (int)(unsigned)(s_key & 0xFFFFFFFFull);
    const int  fmx  = s_mx;
    const int  fmn  = s_mn;
    const bool has  = (fmx > 0);
    const int  mvjF = has ? (fmx - 1) : 0;
    const int  mvjB = has ? (NS - 1 - fmn) : 0;

    const float total = cum[NP - 1];
    float entryF;
    {
        int k = seg0;
        float ax = rx[k], ay = ry[k], az = rz[k];
        float svx = rx[k + 1] - ax, svy = ry[k + 1] - ay, svz = rz[k + 1] - az;
        float svdot = fmaxf(svx * svx + svy * svy + svz * svz, 1e-12f);
        float t0 = ((p0x - ax) * svx + (p0y - ay) * svy + (p0z - az) * svz) / svdot;
        t0 = fminf(fmaxf(t0, 0.0f), 1.0f);
        float c0 = (k == 0) ? 0.0f : cum[k - 1];
        entryF = c0 + t0 * sl[k];
    }

    // ---- walks: warps 0-3 fwd (b2=b), warps 4-7 bwd (b2=b+16)
    const bool  isB = (tid >= TT);
    const int   t   = tid & (TT - 1);
    const int   b2  = isB ? (b + NBR) : b;
    const float entry = isB ? (total - entryF) : entryF;
    const int   mvj   = isB ? mvjB : mvjF;

    float tcv = (t == 0) ? 0.0f : tcs_s[t - 1];
    float tgt = fmaxf(fminf(entry + tcv, total), 0.0f);

    // Search target & predicate:
    //  fwd: largest k in [0,255] with cum_s(k) <= tgt
    //  bwd: largest k in [0,255] with cum_s(k) <  u (u = total - tgt); j = u>0 ? 254-k : 255
    const float T = isB ? (total - tgt) : tgt;
    // OK(v): v < T, or v == T for fwd (<=). isB is warp-uniform.
    #define OKP(v) (isB ? ((v) < T) : ((v) <= T))

    int k = 0;
    {
        // Round A: 3 bits via 7 broadcast probes (independent LDS)
        float v128 = cum[127], v64 = cum[63], v192 = cum[191];
        float v32 = cum[31], v96 = cum[95], v160 = cum[159], v224 = cum[223];
        bool b1 = OKP(v128); k = b1 ? 128 : 0;
        float s2 = b1 ? v192 : v64;
        bool b2 = OKP(s2);  k += b2 ? 64 : 0;
        float s3 = b1 ? (b2 ? v224 : v160) : (b2 ? v96 : v32);
        bool b3 = OKP(s3);  k += b3 ? 32 : 0;
        // Round B: 2 bits via 3 probes
        float p16 = cum[k + 15], p8 = cum[k + 7], p24 = cum[k + 23];
        bool b4 = OKP(p16); k += b4 ? 16 : 0;
        float s5 = b4 ? p24 : p8;
        bool b5 = OKP(s5);  k += b5 ? 8 : 0;
        // Round C: 2 bits via 3 probes
        float q4 = cum[k + 3], q2 = cum[k + 1], q6 = cum[k + 5];
        bool b6 = OKP(q4);  k += b6 ? 4 : 0;
        float s7 = b6 ? q6 : q2;
        bool b7 = OKP(s7);  k += b7 ? 2 : 0;
        // Round D: last bit
        bool b8 = OKP(cum[k]);
        k += b8 ? 1 : 0;
    }
    #undef OKP

    int j = isB ? ((T > 0.0f) ? (NS - 1 - k) : NS) : k;
    j = min(j, mvj);

    float cj  = (j == 0) ? 0.0f : (isB ? (total - cum[NS - 1 - j]) : cum[j - 1]);
    float slj = isB ? sl[NS - 1 - j] : sl[j];
    float tl  = fminf(fmaxf((tgt - cj) / fmaxf(slj, 1e-9f), 0.0f), 1.0f);
    float prx, pry, prz;
    if (isB) {
        int r = NP - 1 - j;                 // a_bw[j] = P[255-j], next = P[254-j]
        float ax = rx[r], ay = ry[r], az = rz[r];
        prx = ax + tl * (rx[r - 1] - ax);
        pry = ay + tl * (ry[r - 1] - ay);
        prz = az + tl * (rz[r - 1] - az);
    } else {
        float ax = rx[j], ay = ry[j], az = rz[j];
        prx = ax + tl * (rx[j + 1] - ax);
        pry = ay + tl * (ry[j + 1] - ay);
        prz = az + tl * (rz[j + 1] - az);
    }
    {
        size_t po = ((size_t)(n * NB2 + b2) * TT + t) * 3;
        g_proj[po + 0] = prx;
        g_proj[po + 1] = pry;
        g_proj[po + 2] = prz;
    }
    float dx = px[t] - prx, dy = py[t] - pry, dz = pz[t] - prz;
    float dist = sqrtf(dx * dx + dy * dy + dz * dz);

    // deterministic dist sums (warp shfl + fixed-order combine)
    #pragma unroll
    for (int off = 16; off > 0; off >>= 1)
        dist += __shfl_xor_sync(FULLMASK, dist, off);
    if (lane == 0) wsum[w] = dist;
    __syncthreads();                                            // B4

    if (tid == 0) {
        float cf = wsum[0] + wsum[1] + wsum[2] + wsum[3];
        float cb = wsum[4] + wsum[5] + wsum[6] + wsum[7];
        g_cost[n * NB2 + b]       = has ? cf : BIGF;
        g_cost[n * NB2 + b + NBR] = has ? cb : BIGF;
        __threadfence();                       // release g_proj + g_cost
        int old = atomicAdd(&g_cnt[n], 1);
        sh_pick = (old == NBR - 1);
    }
    __syncthreads();                                            // B5

    if (!sh_pick) return;

    // ---- picker CTA for sample n: 32-way argmin + gather
    __threadfence();                           // acquire
    if (w == 0) {
        float cv = __ldcg(&g_cost[n * NB2 + lane]);
        float pbd = cv; int pbi = lane;
        #pragma unroll
        for (int off = 16; off > 0; off >>= 1) {
            float od = __shfl_xor_sync(FULLMASK, pbd, off);
            int   oi = __shfl_xor_sync(FULLMASK, pbi, off);
            if (od < pbd || (od == pbd && oi < pbi)) { pbd = od; pbi = oi; }
        }
        if (lane == 0) { sh_b = pbi; sh_hasb = (pbd < BIGF); }
    }
    __syncthreads();                                            // B6

    if (tid < TT) {
        size_t oo = (size_t)(n * TT + tid) * 3;
        if (sh_hasb) {
            size_t po = ((size_t)(n * NB2 + sh_b) * TT + tid) * 3;
            out[oo + 0] = __ldcg(&g_proj[po + 0]);
            out[oo + 1] = __ldcg(&g_proj[po + 1]);
            out[oo + 2] = __ldcg(&g_proj[po + 2]);
        } else {
            out[oo + 0] = px[tid];
            out[oo + 1] = py[tid];
            out[oo + 2] = pz[tid];
        }
    }
    if (tid == 0) g_cnt[n] = 0;                // reset for next graph replay
}

extern "C" void kernel_launch(void* const* d_in, const int* in_sizes, int n_in,
                              void* d_out, int out_size)
{
    const float*         traj = (const float*)d_in[0];
    const float*         road = (const float*)d_in[1];
    const unsigned char* mask = (const unsigned char*)d_in[2];
    float* out = (float*)d_out;

    dim3 grid(NBR, NN);
    fused_arc_kernel<<<grid, 256>>>(traj, road, mask, out);
}